// round 3
// baseline (speedup 1.0000x reference)
#include <cuda_runtime.h>
#include <cstdint>
#include <math.h>

#define MAXN 100000
#define IN_DIM 512

// ---------------- scratch (no allocation allowed -> __device__ globals) ------
__device__ float g_bufA[MAXN * 64];
__device__ float g_bufB[MAXN * 64];
__device__ int   g_rp[MAXN + 1];
__device__ float g_stats[384];        // 3 layers x (64 sum + 64 sumsq)

// ---------------- f32x2 packed FMA (Blackwell FFMA2, PTX-only) ---------------
__device__ __forceinline__ float2 ffma2(float2 a, float2 b, float2 c) {
    unsigned long long ua = *reinterpret_cast<unsigned long long*>(&a);
    unsigned long long ub = *reinterpret_cast<unsigned long long*>(&b);
    unsigned long long uc = *reinterpret_cast<unsigned long long*>(&c);
    unsigned long long ud;
    asm("fma.rn.f32x2 %0, %1, %2, %3;" : "=l"(ud) : "l"(ua), "l"(ub), "l"(uc));
    return *reinterpret_cast<float2*>(&ud);
}

// ---------------- row_ptr from sorted edge_row (lower_bound) -----------------
__global__ void build_rowptr(const int* __restrict__ erow, int E, int n, int* __restrict__ rp) {
    int i = blockIdx.x * blockDim.x + threadIdx.x;
    if (i > n) return;
    int lo = 0, hi = E;
    while (lo < hi) { int mid = (lo + hi) >> 1; if (erow[mid] < i) lo = mid + 1; else hi = mid; }
    rp[i] = lo;
}

__global__ void zero_stats() { int i = threadIdx.x; if (i < 384) g_stats[i] = 0.f; }

// ---------------- GEMM1: [M,512] x [512,64] -> [M,64], fp32 via FFMA2 --------
__global__ void __launch_bounds__(256) gemm1_kernel(
    const float* __restrict__ A, const float* __restrict__ B,
    float* __restrict__ C, int M) {
    const int K = 512, NN = 64, BK = 16, BM = 128;
    __shared__ float As[BK][BM + 4];   // transposed: [k][m]
    __shared__ float Bs[BK][NN];

    int tid = threadIdx.x;
    int tr = tid >> 3;                 // 0..31 (4 rows each)
    int tc = tid & 7;                  // 0..7  (8 cols each)
    int rowBase = blockIdx.x * BM;

    float2 acc[4][4];
#pragma unroll
    for (int i = 0; i < 4; ++i)
#pragma unroll
        for (int j = 0; j < 4; ++j) acc[i][j] = make_float2(0.f, 0.f);

    int la_row = tid >> 2;             // 0..63 (loads 2 rows: +0, +64)
    int la_k   = (tid & 3) * 4;
    int lb_k   = tid >> 4;             // 0..15
    int lb_c   = (tid & 15) * 4;

    for (int kt = 0; kt < K; kt += BK) {
#pragma unroll
        for (int rr = 0; rr < 2; ++rr) {
            int r = la_row + rr * 64;
            int grow = rowBase + r;
            float4 v = make_float4(0.f, 0.f, 0.f, 0.f);
            if (grow < M)
                v = *(const float4*)(A + (size_t)grow * K + kt + la_k);
            As[la_k + 0][r] = v.x;
            As[la_k + 1][r] = v.y;
            As[la_k + 2][r] = v.z;
            As[la_k + 3][r] = v.w;
        }
        float4 bv = *(const float4*)(B + (size_t)(kt + lb_k) * NN + lb_c);
        *(float4*)&Bs[lb_k][lb_c] = bv;
        __syncthreads();

#pragma unroll
        for (int k = 0; k < BK; ++k) {
            float4 a4 = *(const float4*)&As[k][tr * 4];
            float2 b2[4];
            *(float4*)&b2[0] = *(const float4*)&Bs[k][tc * 8];
            *(float4*)&b2[2] = *(const float4*)&Bs[k][tc * 8 + 4];
            float av[4] = {a4.x, a4.y, a4.z, a4.w};
#pragma unroll
            for (int i = 0; i < 4; ++i) {
                float2 ad = make_float2(av[i], av[i]);
#pragma unroll
                for (int j = 0; j < 4; ++j) acc[i][j] = ffma2(ad, b2[j], acc[i][j]);
            }
        }
        __syncthreads();
    }

#pragma unroll
    for (int i = 0; i < 4; ++i) {
        int grow = rowBase + tr * 4 + i;
        if (grow < M) {
            float* cp = C + (size_t)grow * 64 + tc * 8;
            *(float4*)cp       = *(float4*)&acc[i][0];
            *(float4*)(cp + 4) = *(float4*)&acc[i][2];
        }
    }
}

// ---------------- SpMM kernels (vectorized float4 gathers) -------------------
// D=64: warp per node; two half-warps, each gathers a full 256B row via float4.
__global__ void spmm64(const float* __restrict__ sup, const int* __restrict__ ecol,
                       const float* __restrict__ ev, const int* __restrict__ rp,
                       float* __restrict__ out, int n) {
    int gw = (blockIdx.x * blockDim.x + threadIdx.x) >> 5;
    int lane = threadIdx.x & 31;
    if (gw >= n) return;
    int s = rp[gw], e = rp[gw + 1];
    int h = lane >> 4, sl = (lane & 15) * 4;
    float4 acc = make_float4(0.f, 0.f, 0.f, 0.f);
    int j = s + h;
    for (; j + 2 < e; j += 4) {
        int   c0 = ecol[j],     c1 = ecol[j + 2];
        float v0 = ev[j],       v1 = ev[j + 2];
        float4 r0 = *(const float4*)(sup + (size_t)c0 * 64 + sl);
        float4 r1 = *(const float4*)(sup + (size_t)c1 * 64 + sl);
        acc.x = fmaf(v0, r0.x, acc.x); acc.y = fmaf(v0, r0.y, acc.y);
        acc.z = fmaf(v0, r0.z, acc.z); acc.w = fmaf(v0, r0.w, acc.w);
        acc.x = fmaf(v1, r1.x, acc.x); acc.y = fmaf(v1, r1.y, acc.y);
        acc.z = fmaf(v1, r1.z, acc.z); acc.w = fmaf(v1, r1.w, acc.w);
    }
    for (; j < e; j += 2) {
        int c = ecol[j]; float v = ev[j];
        float4 r = *(const float4*)(sup + (size_t)c * 64 + sl);
        acc.x = fmaf(v, r.x, acc.x); acc.y = fmaf(v, r.y, acc.y);
        acc.z = fmaf(v, r.z, acc.z); acc.w = fmaf(v, r.w, acc.w);
    }
    acc.x += __shfl_down_sync(0xffffffffu, acc.x, 16);
    acc.y += __shfl_down_sync(0xffffffffu, acc.y, 16);
    acc.z += __shfl_down_sync(0xffffffffu, acc.z, 16);
    acc.w += __shfl_down_sync(0xffffffffu, acc.w, 16);
    if (lane < 16) *(float4*)(out + (size_t)gw * 64 + sl) = acc;
}

// D=32: warp per node; 4 groups of 8 lanes, 4 edges in flight.
__global__ void spmm32(const float* __restrict__ sup, const int* __restrict__ ecol,
                       const float* __restrict__ ev, const int* __restrict__ rp,
                       float* __restrict__ out, int n) {
    int gw = (blockIdx.x * blockDim.x + threadIdx.x) >> 5;
    int lane = threadIdx.x & 31;
    if (gw >= n) return;
    int s = rp[gw], e = rp[gw + 1];
    int g = lane >> 3, sl = (lane & 7) * 4;
    float4 acc = make_float4(0.f, 0.f, 0.f, 0.f);
    for (int j = s + g; j < e; j += 4) {
        int c = ecol[j]; float v = ev[j];
        float4 r = *(const float4*)(sup + (size_t)c * 32 + sl);
        acc.x = fmaf(v, r.x, acc.x); acc.y = fmaf(v, r.y, acc.y);
        acc.z = fmaf(v, r.z, acc.z); acc.w = fmaf(v, r.w, acc.w);
    }
    acc.x += __shfl_down_sync(0xffffffffu, acc.x, 16);
    acc.y += __shfl_down_sync(0xffffffffu, acc.y, 16);
    acc.z += __shfl_down_sync(0xffffffffu, acc.z, 16);
    acc.w += __shfl_down_sync(0xffffffffu, acc.w, 16);
    acc.x += __shfl_down_sync(0xffffffffu, acc.x, 8);
    acc.y += __shfl_down_sync(0xffffffffu, acc.y, 8);
    acc.z += __shfl_down_sync(0xffffffffu, acc.z, 8);
    acc.w += __shfl_down_sync(0xffffffffu, acc.w, 8);
    if (lane < 8) *(float4*)(out + (size_t)gw * 32 + sl) = acc;
}

// D=16: warp per node; 8 groups of 4 lanes, 8 edges in flight.
__global__ void spmm16(const float* __restrict__ sup, const int* __restrict__ ecol,
                       const float* __restrict__ ev, const int* __restrict__ rp,
                       float* __restrict__ out, int n) {
    int gw = (blockIdx.x * blockDim.x + threadIdx.x) >> 5;
    int lane = threadIdx.x & 31;
    if (gw >= n) return;
    int s = rp[gw], e = rp[gw + 1];
    int g = lane >> 2, sl = (lane & 3) * 4;
    float4 acc = make_float4(0.f, 0.f, 0.f, 0.f);
    for (int j = s + g; j < e; j += 8) {
        int c = ecol[j]; float v = ev[j];
        float4 r = *(const float4*)(sup + (size_t)c * 16 + sl);
        acc.x = fmaf(v, r.x, acc.x); acc.y = fmaf(v, r.y, acc.y);
        acc.z = fmaf(v, r.z, acc.z); acc.w = fmaf(v, r.w, acc.w);
    }
#pragma unroll
    for (int o = 16; o >= 4; o >>= 1) {
        acc.x += __shfl_down_sync(0xffffffffu, acc.x, o);
        acc.y += __shfl_down_sync(0xffffffffu, acc.y, o);
        acc.z += __shfl_down_sync(0xffffffffu, acc.z, o);
        acc.w += __shfl_down_sync(0xffffffffu, acc.w, o);
    }
    if (lane < 4) *(float4*)(out + (size_t)gw * 16 + sl) = acc;
}

// D=40 + fused log_softmax: warp per node.
__global__ void spmm40_lsm(const float* __restrict__ sup, const int* __restrict__ ecol,
                           const float* __restrict__ ev, const int* __restrict__ rp,
                           float* __restrict__ out, int n) {
    int gw = (blockIdx.x * blockDim.x + threadIdx.x) >> 5;
    int lane = threadIdx.x & 31;
    if (gw >= n) return;
    int s = rp[gw], e = rp[gw + 1];
    float acc0 = 0.f, acc1 = 0.f;
    int j = s;
    for (; j + 4 <= e; j += 4) {
        int c0 = ecol[j], c1 = ecol[j + 1], c2 = ecol[j + 2], c3 = ecol[j + 3];
        float v0 = ev[j], v1 = ev[j + 1], v2 = ev[j + 2], v3 = ev[j + 3];
        const float* r0 = sup + (size_t)c0 * 40;
        const float* r1 = sup + (size_t)c1 * 40;
        const float* r2 = sup + (size_t)c2 * 40;
        const float* r3 = sup + (size_t)c3 * 40;
        acc0 = fmaf(v0, r0[lane], acc0); acc0 = fmaf(v1, r1[lane], acc0);
        acc0 = fmaf(v2, r2[lane], acc0); acc0 = fmaf(v3, r3[lane], acc0);
        if (lane < 8) {
            acc1 = fmaf(v0, r0[lane + 32], acc1); acc1 = fmaf(v1, r1[lane + 32], acc1);
            acc1 = fmaf(v2, r2[lane + 32], acc1); acc1 = fmaf(v3, r3[lane + 32], acc1);
        }
    }
    for (; j < e; ++j) {
        int c = ecol[j]; float v = ev[j];
        const float* r = sup + (size_t)c * 40;
        acc0 = fmaf(v, r[lane], acc0);
        if (lane < 8) acc1 = fmaf(v, r[lane + 32], acc1);
    }
    float a1 = (lane < 8) ? acc1 : __int_as_float(0xff800000);
    float m = fmaxf(acc0, a1);
#pragma unroll
    for (int o = 16; o; o >>= 1) m = fmaxf(m, __shfl_xor_sync(0xffffffffu, m, o));
    float ssum = expf(acc0 - m) + ((lane < 8) ? expf(acc1 - m) : 0.f);
#pragma unroll
    for (int o = 16; o; o >>= 1) ssum += __shfl_xor_sync(0xffffffffu, ssum, o);
    float lse = logf(ssum) + m;
    out[(size_t)gw * 40 + lane] = acc0 - lse;
    if (lane < 8) out[(size_t)gw * 40 + 32 + lane] = acc1 - lse;
}

// ---------------- column stats: sum & sumsq per channel ----------------------
template <int D>
__global__ void col_stats(const float* __restrict__ h, int n, int layer) {
    __shared__ float ss[256], sq[256];
    const int REPS = 256 / D;
    int tid = threadIdx.x;
    int ch = tid % D, rep = tid / D;
    int chunk = (n + gridDim.x - 1) / gridDim.x;
    int r0 = blockIdx.x * chunk;
    int r1 = min(n, r0 + chunk);
    float s = 0.f, q = 0.f;
    for (int r = r0 + rep; r < r1; r += REPS) {
        float v = h[(size_t)r * D + ch];
        s += v; q = fmaf(v, v, q);
    }
    ss[tid] = s; sq[tid] = q;
    __syncthreads();
    if (tid < D) {
        float S = 0.f, Q = 0.f;
#pragma unroll
        for (int i = 0; i < REPS; ++i) { S += ss[tid + i * D]; Q += sq[tid + i * D]; }
        atomicAdd(&g_stats[layer * 128 + ch], S);
        atomicAdd(&g_stats[layer * 128 + 64 + ch], Q);
    }
}

// ---------------- fused BN+ELU + small GEMM (warp per node) ------------------
template <int IN, int OUT>
__global__ void gemm_small_fused(const float* __restrict__ h, const float* __restrict__ W,
                                 const float* __restrict__ gamma, const float* __restrict__ beta,
                                 int layer, float* __restrict__ out, int n) {
    __shared__ float Ws[IN * OUT];
    __shared__ float sc[IN], sh[IN];
    int tid = threadIdx.x;
    for (int i = tid; i < IN * OUT; i += blockDim.x) Ws[i] = W[i];
    if (tid < IN) {
        float invn = 1.0f / (float)n;
        float mean = g_stats[layer * 128 + tid] * invn;
        float var  = g_stats[layer * 128 + 64 + tid] * invn - mean * mean;
        float k    = rsqrtf(var + 1e-5f) * gamma[tid];
        sc[tid] = k;
        sh[tid] = beta[tid] - mean * k;
    }
    __syncthreads();
    int gw = (blockIdx.x * blockDim.x + tid) >> 5;
    int lane = tid & 31;
    if (gw >= n) return;
    const float* hr = h + (size_t)gw * IN;
    float acc0 = 0.f, acc1 = 0.f;
#pragma unroll
    for (int k = 0; k < IN; k += 4) {
        float4 h4 = *(const float4*)(hr + k);
        float y0 = fmaf(h4.x, sc[k + 0], sh[k + 0]);
        float y1 = fmaf(h4.y, sc[k + 1], sh[k + 1]);
        float y2 = fmaf(h4.z, sc[k + 2], sh[k + 2]);
        float y3 = fmaf(h4.w, sc[k + 3], sh[k + 3]);
        y0 = y0 > 0.f ? y0 : expm1f(y0);
        y1 = y1 > 0.f ? y1 : expm1f(y1);
        y2 = y2 > 0.f ? y2 : expm1f(y2);
        y3 = y3 > 0.f ? y3 : expm1f(y3);
        acc0 = fmaf(y0, Ws[(k + 0) * OUT + lane], acc0);
        acc0 = fmaf(y1, Ws[(k + 1) * OUT + lane], acc0);
        acc0 = fmaf(y2, Ws[(k + 2) * OUT + lane], acc0);
        acc0 = fmaf(y3, Ws[(k + 3) * OUT + lane], acc0);
        if (OUT > 32 && lane + 32 < OUT) {
            acc1 = fmaf(y0, Ws[(k + 0) * OUT + lane + 32], acc1);
            acc1 = fmaf(y1, Ws[(k + 1) * OUT + lane + 32], acc1);
            acc1 = fmaf(y2, Ws[(k + 2) * OUT + lane + 32], acc1);
            acc1 = fmaf(y3, Ws[(k + 3) * OUT + lane + 32], acc1);
        }
    }
    if (lane < OUT) out[(size_t)gw * OUT + lane] = acc0;
    if (OUT > 32 && lane + 32 < OUT) out[(size_t)gw * OUT + lane + 32] = acc1;
}

// ---------------- launch ------------------------------------------------------
static inline int dg(long long t, int b) { return (int)((t + b - 1) / b); }

extern "C" void kernel_launch(void* const* d_in, const int* in_sizes, int n_in,
                              void* d_out, int out_size) {
    const float* x    = (const float*)d_in[0];
    const int*   erow = (const int*)d_in[1];
    const int*   ecol = (const int*)d_in[2];
    const float* ev   = (const float*)d_in[3];
    const float* W1   = (const float*)d_in[4];
    const float* W2   = (const float*)d_in[5];
    const float* W3   = (const float*)d_in[6];
    const float* W4   = (const float*)d_in[7];
    const float* g1   = (const float*)d_in[8];
    const float* b1   = (const float*)d_in[9];
    const float* g2   = (const float*)d_in[10];
    const float* b2   = (const float*)d_in[11];
    const float* g3   = (const float*)d_in[12];
    const float* b3   = (const float*)d_in[13];

    int n = in_sizes[0] / IN_DIM;
    int E = in_sizes[1];
    float* out = (float*)d_out;

    float* hA; float* hB; int* rp;
    cudaGetSymbolAddress((void**)&hA, g_bufA);
    cudaGetSymbolAddress((void**)&hB, g_bufB);
    cudaGetSymbolAddress((void**)&rp, g_rp);

    const int TB = 256;
    const int STATS_BLOCKS = 512;

    build_rowptr<<<dg(n + 1, TB), TB>>>(erow, E, n, rp);
    zero_stats<<<1, 384>>>();

    // ---- layer 1: x @ W1 -> spmm -> stats ----
    gemm1_kernel<<<dg(n, 128), 256>>>(x, W1, hA, n);
    spmm64<<<dg((long long)n * 32, TB), TB>>>(hA, ecol, ev, rp, hB, n);
    col_stats<64><<<STATS_BLOCKS, 256>>>(hB, n, 0);

    // ---- layer 2: fused bn+elu+gemm(64->32) -> spmm -> stats ----
    gemm_small_fused<64, 32><<<dg((long long)n * 32, TB), TB>>>(hB, W2, g1, b1, 0, hA, n);
    spmm32<<<dg((long long)n * 32, TB), TB>>>(hA, ecol, ev, rp, hB, n);
    col_stats<32><<<STATS_BLOCKS, 256>>>(hB, n, 1);

    // ---- layer 3: fused bn+elu+gemm(32->16) -> spmm -> stats ----
    gemm_small_fused<32, 16><<<dg((long long)n * 32, TB), TB>>>(hB, W3, g2, b2, 1, hA, n);
    spmm16<<<dg((long long)n * 32, TB), TB>>>(hA, ecol, ev, rp, hB, n);
    col_stats<16><<<STATS_BLOCKS, 256>>>(hB, n, 2);

    // ---- layer 4: fused bn+elu+gemm(16->40) -> spmm + log_softmax ----
    gemm_small_fused<16, 40><<<dg((long long)n * 32, TB), TB>>>(hB, W4, g3, b3, 2, hA, n);
    spmm40_lsm<<<dg((long long)n * 32, TB), TB>>>(hA, ecol, ev, rp, out, n);
}

// round 4
// speedup vs baseline: 1.1378x; 1.1378x over previous
#include <cuda_runtime.h>
#include <cstdint>
#include <math.h>

#define MAXN 100000
#define IN_DIM 512

// ---------------- scratch ----------------------------------------------------
__device__ float g_bufA[MAXN * 64];
__device__ float g_bufB[MAXN * 64];
__device__ int   g_rp[MAXN + 1];
__device__ float g_stats[384];        // 3 layers x (64 sum + 64 sumsq)

// ---------------- f32x2 packed FMA (Blackwell FFMA2, PTX-only) ---------------
__device__ __forceinline__ float2 ffma2(float2 a, float2 b, float2 c) {
    unsigned long long ua = *reinterpret_cast<unsigned long long*>(&a);
    unsigned long long ub = *reinterpret_cast<unsigned long long*>(&b);
    unsigned long long uc = *reinterpret_cast<unsigned long long*>(&c);
    unsigned long long ud;
    asm("fma.rn.f32x2 %0, %1, %2, %3;" : "=l"(ud) : "l"(ua), "l"(ub), "l"(uc));
    return *reinterpret_cast<float2*>(&ud);
}

// ---------------- row_ptr from sorted edge_row -------------------------------
__global__ void build_rowptr(const int* __restrict__ erow, int E, int n, int* __restrict__ rp) {
    int i = blockIdx.x * blockDim.x + threadIdx.x;
    if (i > n) return;
    int lo = 0, hi = E;
    while (lo < hi) { int mid = (lo + hi) >> 1; if (erow[mid] < i) lo = mid + 1; else hi = mid; }
    rp[i] = lo;
}

__global__ void zero_stats() { int i = threadIdx.x; if (i < 384) g_stats[i] = 0.f; }

// ---------------- GEMM1: [M,512]x[512,64], 256x64 block, 8x8 thread tile -----
__global__ void __launch_bounds__(256) gemm1_kernel(
    const float* __restrict__ A, const float* __restrict__ B,
    float* __restrict__ C, int M) {
    const int K = 512;
    __shared__ float As[16][260];   // [k][m], 16B-aligned rows (260*4=1040)
    __shared__ float Bs[16][64];

    int tid = threadIdx.x;
    int tm = tid & 31;              // lane -> 8 m-rows (4 + 4 split by +128)
    int tn = tid >> 5;              // warp -> 8 n-cols
    int rowBase = blockIdx.x * 256;

    float2 acc[8][4];
#pragma unroll
    for (int i = 0; i < 8; ++i)
#pragma unroll
        for (int j = 0; j < 4; ++j) acc[i][j] = make_float2(0.f, 0.f);

    for (int kt = 0; kt < K; kt += 16) {
#pragma unroll
        for (int i = 0; i < 4; ++i) {          // A: 256 rows x 16 k = 1024 float4
            int idx = tid + i * 256;
            int row = idx >> 2, kc = idx & 3;
            int grow = rowBase + row;
            float4 v = make_float4(0.f, 0.f, 0.f, 0.f);
            if (grow < M) v = *(const float4*)(A + (size_t)grow * K + kt + kc * 4);
            As[kc * 4 + 0][row] = v.x;
            As[kc * 4 + 1][row] = v.y;
            As[kc * 4 + 2][row] = v.z;
            As[kc * 4 + 3][row] = v.w;
        }
        {                                       // B: 16 k x 64 n = 256 float4
            int row = tid >> 4, c = (tid & 15) * 4;
            *(float4*)&Bs[row][c] = *(const float4*)(B + (size_t)(kt + row) * 64 + c);
        }
        __syncthreads();

#pragma unroll
        for (int k = 0; k < 16; ++k) {
            float4 alo = *(const float4*)&As[k][tm * 4];
            float4 ahi = *(const float4*)&As[k][128 + tm * 4];
            float2 b2[4];
            *(float4*)&b2[0] = *(const float4*)&Bs[k][tn * 8];
            *(float4*)&b2[2] = *(const float4*)&Bs[k][tn * 8 + 4];
            float alof[4] = {alo.x, alo.y, alo.z, alo.w};
            float ahif[4] = {ahi.x, ahi.y, ahi.z, ahi.w};
#pragma unroll
            for (int i = 0; i < 4; ++i) {
                float2 ad = make_float2(alof[i], alof[i]);
#pragma unroll
                for (int j = 0; j < 4; ++j) acc[i][j] = ffma2(ad, b2[j], acc[i][j]);
            }
#pragma unroll
            for (int i = 0; i < 4; ++i) {
                float2 ad = make_float2(ahif[i], ahif[i]);
#pragma unroll
                for (int j = 0; j < 4; ++j) acc[4 + i][j] = ffma2(ad, b2[j], acc[4 + i][j]);
            }
        }
        __syncthreads();
    }

#pragma unroll
    for (int i = 0; i < 4; ++i) {
        int g0 = rowBase + tm * 4 + i;
        if (g0 < M) {
            float* cp = C + (size_t)g0 * 64 + tn * 8;
            *(float4*)cp       = *(float4*)&acc[i][0];
            *(float4*)(cp + 4) = *(float4*)&acc[i][2];
        }
        int g1 = rowBase + 128 + tm * 4 + i;
        if (g1 < M) {
            float* cp = C + (size_t)g1 * 64 + tn * 8;
            *(float4*)cp       = *(float4*)&acc[4 + i][0];
            *(float4*)(cp + 4) = *(float4*)&acc[4 + i][2];
        }
    }
}

// ---------------- SpMM kernels (float4 gathers) + optional fused stats -------
// D=64: warp per node; two half-warps each gather full 256B rows.
template <bool STATS>
__global__ void __launch_bounds__(256) spmm64(
    const float* __restrict__ sup, const int* __restrict__ ecol,
    const float* __restrict__ ev, const int* __restrict__ rp,
    float* __restrict__ out, int n, int layer) {
    __shared__ float s_sum[64], s_sq[64];
    int tid = threadIdx.x;
    if (STATS) { if (tid < 64) { s_sum[tid] = 0.f; s_sq[tid] = 0.f; } __syncthreads(); }
    int gw = (blockIdx.x * blockDim.x + tid) >> 5;
    int lane = tid & 31;
    int h = lane >> 4, sl = (lane & 15) * 4;
    float4 acc = make_float4(0.f, 0.f, 0.f, 0.f);
    if (gw < n) {
        int s = rp[gw], e = rp[gw + 1];
        int j = s + h;
        for (; j + 2 < e; j += 4) {
            int   c0 = ecol[j],     c1 = ecol[j + 2];
            float v0 = ev[j],       v1 = ev[j + 2];
            float4 r0 = *(const float4*)(sup + (size_t)c0 * 64 + sl);
            float4 r1 = *(const float4*)(sup + (size_t)c1 * 64 + sl);
            acc.x = fmaf(v0, r0.x, acc.x); acc.y = fmaf(v0, r0.y, acc.y);
            acc.z = fmaf(v0, r0.z, acc.z); acc.w = fmaf(v0, r0.w, acc.w);
            acc.x = fmaf(v1, r1.x, acc.x); acc.y = fmaf(v1, r1.y, acc.y);
            acc.z = fmaf(v1, r1.z, acc.z); acc.w = fmaf(v1, r1.w, acc.w);
        }
        for (; j < e; j += 2) {
            int c = ecol[j]; float v = ev[j];
            float4 r = *(const float4*)(sup + (size_t)c * 64 + sl);
            acc.x = fmaf(v, r.x, acc.x); acc.y = fmaf(v, r.y, acc.y);
            acc.z = fmaf(v, r.z, acc.z); acc.w = fmaf(v, r.w, acc.w);
        }
        acc.x += __shfl_down_sync(0xffffffffu, acc.x, 16);
        acc.y += __shfl_down_sync(0xffffffffu, acc.y, 16);
        acc.z += __shfl_down_sync(0xffffffffu, acc.z, 16);
        acc.w += __shfl_down_sync(0xffffffffu, acc.w, 16);
        if (lane < 16) {
            *(float4*)(out + (size_t)gw * 64 + sl) = acc;
            if (STATS) {
                atomicAdd(&s_sum[sl + 0], acc.x); atomicAdd(&s_sq[sl + 0], acc.x * acc.x);
                atomicAdd(&s_sum[sl + 1], acc.y); atomicAdd(&s_sq[sl + 1], acc.y * acc.y);
                atomicAdd(&s_sum[sl + 2], acc.z); atomicAdd(&s_sq[sl + 2], acc.z * acc.z);
                atomicAdd(&s_sum[sl + 3], acc.w); atomicAdd(&s_sq[sl + 3], acc.w * acc.w);
            }
        }
    }
    if (STATS) {
        __syncthreads();
        if (tid < 64) {
            atomicAdd(&g_stats[layer * 128 + tid], s_sum[tid]);
            atomicAdd(&g_stats[layer * 128 + 64 + tid], s_sq[tid]);
        }
    }
}

// D=32: warp per node; 4 groups of 8 lanes, 4 edges in flight.
template <bool STATS>
__global__ void __launch_bounds__(256) spmm32(
    const float* __restrict__ sup, const int* __restrict__ ecol,
    const float* __restrict__ ev, const int* __restrict__ rp,
    float* __restrict__ out, int n, int layer) {
    __shared__ float s_sum[32], s_sq[32];
    int tid = threadIdx.x;
    if (STATS) { if (tid < 32) { s_sum[tid] = 0.f; s_sq[tid] = 0.f; } __syncthreads(); }
    int gw = (blockIdx.x * blockDim.x + tid) >> 5;
    int lane = tid & 31;
    if (gw < n) {
        int s = rp[gw], e = rp[gw + 1];
        int g = lane >> 3, sl = (lane & 7) * 4;
        float4 acc = make_float4(0.f, 0.f, 0.f, 0.f);
        for (int j = s + g; j < e; j += 4) {
            int c = ecol[j]; float v = ev[j];
            float4 r = *(const float4*)(sup + (size_t)c * 32 + sl);
            acc.x = fmaf(v, r.x, acc.x); acc.y = fmaf(v, r.y, acc.y);
            acc.z = fmaf(v, r.z, acc.z); acc.w = fmaf(v, r.w, acc.w);
        }
#pragma unroll
        for (int o = 16; o >= 8; o >>= 1) {
            acc.x += __shfl_down_sync(0xffffffffu, acc.x, o);
            acc.y += __shfl_down_sync(0xffffffffu, acc.y, o);
            acc.z += __shfl_down_sync(0xffffffffu, acc.z, o);
            acc.w += __shfl_down_sync(0xffffffffu, acc.w, o);
        }
        if (lane < 8) {
            *(float4*)(out + (size_t)gw * 32 + sl) = acc;
            if (STATS) {
                atomicAdd(&s_sum[sl + 0], acc.x); atomicAdd(&s_sq[sl + 0], acc.x * acc.x);
                atomicAdd(&s_sum[sl + 1], acc.y); atomicAdd(&s_sq[sl + 1], acc.y * acc.y);
                atomicAdd(&s_sum[sl + 2], acc.z); atomicAdd(&s_sq[sl + 2], acc.z * acc.z);
                atomicAdd(&s_sum[sl + 3], acc.w); atomicAdd(&s_sq[sl + 3], acc.w * acc.w);
            }
        }
    }
    if (STATS) {
        __syncthreads();
        if (tid < 32) {
            atomicAdd(&g_stats[layer * 128 + tid], s_sum[tid]);
            atomicAdd(&g_stats[layer * 128 + 64 + tid], s_sq[tid]);
        }
    }
}

// D=16: warp per node; 8 groups of 4 lanes, 8 edges in flight.
template <bool STATS>
__global__ void __launch_bounds__(256) spmm16(
    const float* __restrict__ sup, const int* __restrict__ ecol,
    const float* __restrict__ ev, const int* __restrict__ rp,
    float* __restrict__ out, int n, int layer) {
    __shared__ float s_sum[16], s_sq[16];
    int tid = threadIdx.x;
    if (STATS) { if (tid < 16) { s_sum[tid] = 0.f; s_sq[tid] = 0.f; } __syncthreads(); }
    int gw = (blockIdx.x * blockDim.x + tid) >> 5;
    int lane = tid & 31;
    if (gw < n) {
        int s = rp[gw], e = rp[gw + 1];
        int g = lane >> 2, sl = (lane & 3) * 4;
        float4 acc = make_float4(0.f, 0.f, 0.f, 0.f);
        for (int j = s + g; j < e; j += 8) {
            int c = ecol[j]; float v = ev[j];
            float4 r = *(const float4*)(sup + (size_t)c * 16 + sl);
            acc.x = fmaf(v, r.x, acc.x); acc.y = fmaf(v, r.y, acc.y);
            acc.z = fmaf(v, r.z, acc.z); acc.w = fmaf(v, r.w, acc.w);
        }
#pragma unroll
        for (int o = 16; o >= 4; o >>= 1) {
            acc.x += __shfl_down_sync(0xffffffffu, acc.x, o);
            acc.y += __shfl_down_sync(0xffffffffu, acc.y, o);
            acc.z += __shfl_down_sync(0xffffffffu, acc.z, o);
            acc.w += __shfl_down_sync(0xffffffffu, acc.w, o);
        }
        if (lane < 4) {
            *(float4*)(out + (size_t)gw * 16 + sl) = acc;
            if (STATS) {
                atomicAdd(&s_sum[sl + 0], acc.x); atomicAdd(&s_sq[sl + 0], acc.x * acc.x);
                atomicAdd(&s_sum[sl + 1], acc.y); atomicAdd(&s_sq[sl + 1], acc.y * acc.y);
                atomicAdd(&s_sum[sl + 2], acc.z); atomicAdd(&s_sq[sl + 2], acc.z * acc.z);
                atomicAdd(&s_sum[sl + 3], acc.w); atomicAdd(&s_sq[sl + 3], acc.w * acc.w);
            }
        }
    }
    if (STATS) {
        __syncthreads();
        if (tid < 16) {
            atomicAdd(&g_stats[layer * 128 + tid], s_sum[tid]);
            atomicAdd(&g_stats[layer * 128 + 64 + tid], s_sq[tid]);
        }
    }
}

// ---------------- fused BN+ELU + small GEMM (warp per node) ------------------
template <int IN, int OUT>
__global__ void gemm_small_fused(const float* __restrict__ h, const float* __restrict__ W,
                                 const float* __restrict__ gamma, const float* __restrict__ beta,
                                 int layer, float* __restrict__ out, int n) {
    __shared__ float Ws[IN * OUT];
    __shared__ float sc[IN], sh[IN];
    int tid = threadIdx.x;
    for (int i = tid; i < IN * OUT; i += blockDim.x) Ws[i] = W[i];
    if (tid < IN) {
        float invn = 1.0f / (float)n;
        float mean = g_stats[layer * 128 + tid] * invn;
        float var  = g_stats[layer * 128 + 64 + tid] * invn - mean * mean;
        float k    = rsqrtf(var + 1e-5f) * gamma[tid];
        sc[tid] = k;
        sh[tid] = beta[tid] - mean * k;
    }
    __syncthreads();
    int gw = (blockIdx.x * blockDim.x + tid) >> 5;
    int lane = tid & 31;
    if (gw >= n) return;
    const float* hr = h + (size_t)gw * IN;
    float acc0 = 0.f;
#pragma unroll
    for (int k = 0; k < IN; k += 4) {
        float4 h4 = *(const float4*)(hr + k);
        float y0 = fmaf(h4.x, sc[k + 0], sh[k + 0]);
        float y1 = fmaf(h4.y, sc[k + 1], sh[k + 1]);
        float y2 = fmaf(h4.z, sc[k + 2], sh[k + 2]);
        float y3 = fmaf(h4.w, sc[k + 3], sh[k + 3]);
        y0 = y0 > 0.f ? y0 : expm1f(y0);
        y1 = y1 > 0.f ? y1 : expm1f(y1);
        y2 = y2 > 0.f ? y2 : expm1f(y2);
        y3 = y3 > 0.f ? y3 : expm1f(y3);
        acc0 = fmaf(y0, Ws[(k + 0) * OUT + lane], acc0);
        acc0 = fmaf(y1, Ws[(k + 1) * OUT + lane], acc0);
        acc0 = fmaf(y2, Ws[(k + 2) * OUT + lane], acc0);
        acc0 = fmaf(y3, Ws[(k + 3) * OUT + lane], acc0);
    }
    if (lane < OUT) out[(size_t)gw * OUT + lane] = acc0;
}

// ---------------- standalone BN+ELU for D=16 (pre layer-4) -------------------
__global__ void bn_elu16(const float* __restrict__ h, float* __restrict__ out,
                         const float* __restrict__ gamma, const float* __restrict__ beta,
                         int n) {
    int i = blockIdx.x * blockDim.x + threadIdx.x;
    if (i >= n * 16) return;
    int ch = i & 15;
    float invn = 1.0f / (float)n;
    float mean = g_stats[256 + ch] * invn;
    float var  = g_stats[256 + 64 + ch] * invn - mean * mean;
    float k = rsqrtf(var + 1e-5f) * gamma[ch];
    float y = fmaf(h[i] - mean, k, beta[ch]);
    out[i] = y > 0.f ? y : expm1f(y);
}

// ---------------- final: [n,16] x [16,40] + log_softmax, warp per node -------
__global__ void gemm40_lsm(const float* __restrict__ h, const float* __restrict__ W,
                           float* __restrict__ out, int n) {
    __shared__ float Ws[16 * 40];
    int tid = threadIdx.x;
    for (int i = tid; i < 16 * 40; i += blockDim.x) Ws[i] = W[i];
    __syncthreads();
    int gw = (blockIdx.x * blockDim.x + tid) >> 5;
    int lane = tid & 31;
    if (gw >= n) return;
    const float* hr = h + (size_t)gw * 16;
    float acc0 = 0.f, acc1 = 0.f;
#pragma unroll
    for (int k = 0; k < 16; k += 4) {
        float4 h4 = *(const float4*)(hr + k);
        acc0 = fmaf(h4.x, Ws[(k + 0) * 40 + lane], acc0);
        acc0 = fmaf(h4.y, Ws[(k + 1) * 40 + lane], acc0);
        acc0 = fmaf(h4.z, Ws[(k + 2) * 40 + lane], acc0);
        acc0 = fmaf(h4.w, Ws[(k + 3) * 40 + lane], acc0);
        if (lane < 8) {
            acc1 = fmaf(h4.x, Ws[(k + 0) * 40 + 32 + lane], acc1);
            acc1 = fmaf(h4.y, Ws[(k + 1) * 40 + 32 + lane], acc1);
            acc1 = fmaf(h4.z, Ws[(k + 2) * 40 + 32 + lane], acc1);
            acc1 = fmaf(h4.w, Ws[(k + 3) * 40 + 32 + lane], acc1);
        }
    }
    float a1 = (lane < 8) ? acc1 : __int_as_float(0xff800000);
    float m = fmaxf(acc0, a1);
#pragma unroll
    for (int o = 16; o; o >>= 1) m = fmaxf(m, __shfl_xor_sync(0xffffffffu, m, o));
    float ssum = expf(acc0 - m) + ((lane < 8) ? expf(acc1 - m) : 0.f);
#pragma unroll
    for (int o = 16; o; o >>= 1) ssum += __shfl_xor_sync(0xffffffffu, ssum, o);
    float lse = logf(ssum) + m;
    out[(size_t)gw * 40 + lane] = acc0 - lse;
    if (lane < 8) out[(size_t)gw * 40 + 32 + lane] = acc1 - lse;
}

// ---------------- launch ------------------------------------------------------
static inline int dg(long long t, int b) { return (int)((t + b - 1) / b); }

extern "C" void kernel_launch(void* const* d_in, const int* in_sizes, int n_in,
                              void* d_out, int out_size) {
    const float* x    = (const float*)d_in[0];
    const int*   erow = (const int*)d_in[1];
    const int*   ecol = (const int*)d_in[2];
    const float* ev   = (const float*)d_in[3];
    const float* W1   = (const float*)d_in[4];
    const float* W2   = (const float*)d_in[5];
    const float* W3   = (const float*)d_in[6];
    const float* W4   = (const float*)d_in[7];
    const float* g1   = (const float*)d_in[8];
    const float* b1   = (const float*)d_in[9];
    const float* g2   = (const float*)d_in[10];
    const float* b2   = (const float*)d_in[11];
    const float* g3   = (const float*)d_in[12];
    const float* b3   = (const float*)d_in[13];

    int n = in_sizes[0] / IN_DIM;
    int E = in_sizes[1];
    float* out = (float*)d_out;

    float* hA; float* hB; int* rp;
    cudaGetSymbolAddress((void**)&hA, g_bufA);
    cudaGetSymbolAddress((void**)&hB, g_bufB);
    cudaGetSymbolAddress((void**)&rp, g_rp);

    const int TB = 256;

    build_rowptr<<<dg(n + 1, TB), TB>>>(erow, E, n, rp);
    zero_stats<<<1, 384>>>();

    // ---- layer 1: x @ W1 -> spmm64 (+stats0) ----
    gemm1_kernel<<<dg(n, 256), 256>>>(x, W1, hA, n);
    spmm64<true><<<dg((long long)n * 32, TB), TB>>>(hA, ecol, ev, rp, hB, n, 0);

    // ---- layer 2: bn0+elu+gemm(64->32) -> spmm32 (+stats1) ----
    gemm_small_fused<64, 32><<<dg((long long)n * 32, TB), TB>>>(hB, W2, g1, b1, 0, hA, n);
    spmm32<true><<<dg((long long)n * 32, TB), TB>>>(hA, ecol, ev, rp, hB, n, 1);

    // ---- layer 3: bn1+elu+gemm(32->16) -> spmm16 (+stats2) ----
    gemm_small_fused<32, 16><<<dg((long long)n * 32, TB), TB>>>(hB, W3, g2, b2, 1, hA, n);
    spmm16<true><<<dg((long long)n * 32, TB), TB>>>(hA, ecol, ev, rp, hB, n, 2);

    // ---- layer 4 (commuted): bn2+elu -> spmm16 -> gemm(16->40)+log_softmax ----
    bn_elu16<<<dg((long long)n * 16, TB), TB>>>(hB, hA, g3, b3, n);
    spmm16<false><<<dg((long long)n * 32, TB), TB>>>(hA, ecol, ev, rp, hB, n, 0);
    gemm40_lsm<<<dg((long long)n * 32, TB), TB>>>(hB, W4, out, n);
}